// round 12
// baseline (speedup 1.0000x reference)
#include <cuda_runtime.h>
#include <cuda_fp16.h>
#include <math.h>
#include <stdint.h>

// ---------------- problem constants ----------------
#define LSEQ   2048
#define DM     768
#define DI     1536          // 2*DM
#define DXZ    3072          // 2*DI
#define DTR    48
#define DS     16
#define DCONV  4
#define NLAYER 2
#define XDBL   80            // DTR + 2*DS
#define NCH    32
#define CLEN   64            // LSEQ / NCH
#define NDB    (DI / 128)    // 12 d-blocks

// ---------------- scratch (device globals, no allocation) ----------------
__device__ __align__(16) float g_x   [LSEQ * DM];    // residual stream
__device__ __align__(16) float g_res [LSEQ * DI];    // in_proj res half (fp32)
__device__ __align__(16) float g_xdbl[LSEQ * XDBL];  // x_proj output (dt | B | C)
__device__ __align__(16) float g_delta[LSEQ * DI];   // softplus(dt@dt_proj + b)
__device__ __align__(16) float g_Hincl[NCH * DI * DS]; // inclusive chunk states
__device__ int g_flags[2][NDB * NCH];                // lookback flags, 2 slots

// fp16 activations
__device__ __align__(16) __half g_xn  [LSEQ * DM];
__device__ __align__(16) __half g_xzh [LSEQ * DI];   // in_proj xr half (fp16, pre-conv)
__device__ __align__(16) __half g_xrh [LSEQ * DI];   // conv+silu output
__device__ __align__(16) __half g_ya  [LSEQ * DI];
__device__ __align__(16) __half g_dt  [LSEQ * 64];   // dt cols padded 48->64
// fp16 weights, transposed [N][K], per-layer buffers (prepared once at start)
__device__ __align__(16) __half g_win [NLAYER * DM * DXZ];
__device__ __align__(16) __half g_wout[NLAYER * DI * DM];
__device__ __align__(16) __half g_wxp [NLAYER * 128 * DI];
__device__ __align__(16) __half g_wdt [NLAYER * DI * 64];
// split-K partials (max: 8 x 2048 x 80; out: 3 x 2048 x 768)
__device__ __align__(16) float g_part[3 * LSEQ * DM];

// ---------------- small helpers ----------------
__device__ __forceinline__ uint32_t smem_u32(const void* p) {
    uint32_t a;
    asm("{ .reg .u64 t; cvta.to.shared.u64 t, %1; cvt.u32.u64 %0, t; }"
        : "=r"(a) : "l"(p));
    return a;
}
__device__ __forceinline__ void ldm4(uint32_t addr, uint32_t r[4]) {
    asm volatile("ldmatrix.sync.aligned.m8n8.x4.shared.b16 {%0,%1,%2,%3}, [%4];"
                 : "=r"(r[0]), "=r"(r[1]), "=r"(r[2]), "=r"(r[3]) : "r"(addr));
}
__device__ __forceinline__ void mma16816(float c[4], const uint32_t a[4],
                                         const uint32_t b0, const uint32_t b1) {
    asm volatile(
        "mma.sync.aligned.m16n8k16.row.col.f32.f16.f16.f32 "
        "{%0,%1,%2,%3}, {%4,%5,%6,%7}, {%8,%9}, {%0,%1,%2,%3};"
        : "+f"(c[0]), "+f"(c[1]), "+f"(c[2]), "+f"(c[3])
        : "r"(a[0]), "r"(a[1]), "r"(a[2]), "r"(a[3]), "r"(b0), "r"(b1));
}

// ---------------- single-term fp16 GEMM via mma.sync ----------------
// Tile 128x128, K-slab 64, 3 stages x 2 tiles, 2 CTAs/SM, fully unrolled S.
#define SROW    72                       // 64 halfs + 8 pad
#define TILE_E  (128 * SROW)             // 18432 B
#define NSTAGE  3
#define SMEM_MMA (NSTAGE * 2 * TILE_E * 2)   // 110592 B

__device__ __forceinline__ void mma_load_stage(
        uint32_t smb, int stage,
        const __half* __restrict__ A, const __half* __restrict__ B,
        int row0, int col0, int k0, int K, int tid) {
    #pragma unroll
    for (int t = 0; t < 2; t++) {
        const __half* src = (t == 0) ? A : B;
        int r0 = (t == 0) ? row0 : col0;
        #pragma unroll
        for (int i = 0; i < 4; i++) {
            int c = tid + i * 256;
            int row = c >> 3, kc = (c & 7) * 8;
            uint32_t dst = smb + (uint32_t)(((stage * 2 + t) * TILE_E) + row * SROW + kc) * 2u;
            const void* gsrc = src + (size_t)(r0 + row) * K + k0 + kc;
            asm volatile("cp.async.cg.shared.global [%0], [%1], 16;"
                         :: "r"(dst), "l"(gsrc));
        }
    }
    asm volatile("cp.async.commit_group;" ::: "memory");
}

// MODE 0: fp32 write  MODE 1: softplus(v+bias)  MODE 2: split fp16-xr / fp32-res
template<int MODE, int S>
__global__ void __launch_bounds__(256, 2)
gemm_fp16_kernel(const __half* __restrict__ Ag, const __half* __restrict__ Bg,
                 float* __restrict__ C, __half* __restrict__ Ch,
                 const float* __restrict__ bias,
                 int K, int ldc, int Nvalid) {
    extern __shared__ __half sm[];
    const int tid = threadIdx.x, lane = tid & 31, wid = tid >> 5;
    const int wm = wid & 3, wn = wid >> 2;
    const int row0 = blockIdx.y * 128, col0 = blockIdx.x * 128;
    const int kb = blockIdx.z * (S * 64);
    C += (size_t)blockIdx.z * LSEQ * ldc;
    uint32_t smb = smem_u32(sm);

    float acc[2][8][4] = {};

    mma_load_stage(smb, 0, Ag, Bg, row0, col0, kb, K, tid);
    if (S > 1) mma_load_stage(smb, 1, Ag, Bg, row0, col0, kb + 64, K, tid);

    const int lrow = lane & 15, lcol0 = (lane >> 4) * 8;

    #pragma unroll
    for (int s = 0; s < S; s++) {
        if (s + 1 < S) {
            asm volatile("cp.async.wait_group 1;" ::: "memory");
        } else {
            asm volatile("cp.async.wait_group 0;" ::: "memory");
        }
        __syncthreads();
        if (s + 2 < S)
            mma_load_stage(smb, (s + 2) % NSTAGE, Ag, Bg,
                           row0, col0, kb + (s + 2) * 64, K, tid);

        int st = s % NSTAGE;
        uint32_t bA = smb + (uint32_t)((st * 2 + 0) * TILE_E) * 2u;
        uint32_t bB = smb + (uint32_t)((st * 2 + 1) * TILE_E) * 2u;

        #pragma unroll
        for (int kh = 0; kh < 64; kh += 32) {
            uint32_t ah[2][2][4];
            uint32_t bb[2][4][4];
            #pragma unroll
            for (int kk2 = 0; kk2 < 2; kk2++) {
                int kk = kh + kk2 * 16;
                #pragma unroll
                for (int mt = 0; mt < 2; mt++) {
                    uint32_t off = (uint32_t)((wm * 32 + mt * 16 + lrow) * SROW + kk + lcol0) * 2u;
                    ldm4(bA + off, ah[kk2][mt]);
                }
                #pragma unroll
                for (int g = 0; g < 4; g++) {
                    uint32_t off = (uint32_t)((wn * 64 + g * 16 + lrow) * SROW + kk + lcol0) * 2u;
                    ldm4(bB + off, bb[kk2][g]);
                }
            }
            #pragma unroll
            for (int kk2 = 0; kk2 < 2; kk2++) {
                #pragma unroll
                for (int g = 0; g < 4; g++) {
                    #pragma unroll
                    for (int mt = 0; mt < 2; mt++) {
                        mma16816(acc[mt][2 * g + 0], ah[kk2][mt], bb[kk2][g][0], bb[kk2][g][2]);
                        mma16816(acc[mt][2 * g + 1], ah[kk2][mt], bb[kk2][g][1], bb[kk2][g][3]);
                    }
                }
            }
        }
    }

    // epilogue
    int gq = lane >> 2, tq = lane & 3;
    #pragma unroll
    for (int mt = 0; mt < 2; mt++) {
        #pragma unroll
        for (int n8 = 0; n8 < 8; n8++) {
            int rm = row0 + wm * 32 + mt * 16 + gq;
            int cn = col0 + wn * 64 + n8 * 8 + 2 * tq;
            if (cn >= Nvalid) continue;
            float v[4] = {acc[mt][n8][0], acc[mt][n8][1],
                          acc[mt][n8][2], acc[mt][n8][3]};
            if (MODE == 1) {
                float b0 = bias[cn], b1 = bias[cn + 1];
                v[0] += b0; v[1] += b1; v[2] += b0; v[3] += b1;
                #pragma unroll
                for (int q = 0; q < 4; q++)
                    v[q] = (v[q] > 20.f) ? v[q] : log1pf(__expf(v[q]));
            }
            if (MODE == 2) {
                if (cn < DI) {   // xr half -> fp16
                    __half2 h0 = __floats2half2_rn(v[0], v[1]);
                    __half2 h1 = __floats2half2_rn(v[2], v[3]);
                    *reinterpret_cast<__half2*>(Ch + (size_t)rm * DI + cn) = h0;
                    *reinterpret_cast<__half2*>(Ch + (size_t)(rm + 8) * DI + cn) = h1;
                } else {         // res half -> fp32
                    int cr = cn - DI;
                    *reinterpret_cast<float2*>(C + (size_t)rm * DI + cr) =
                        make_float2(v[0], v[1]);
                    *reinterpret_cast<float2*>(C + (size_t)(rm + 8) * DI + cr) =
                        make_float2(v[2], v[3]);
                }
            } else {
                *reinterpret_cast<float2*>(C + (size_t)rm * ldc + cn) =
                    make_float2(v[0], v[1]);
                *reinterpret_cast<float2*>(C + (size_t)(rm + 8) * ldc + cn) =
                    make_float2(v[2], v[3]);
            }
        }
    }
}

// reduce 8 x_proj split-K partials -> g_xdbl, emit fp16 dt cols (pad 64)
__global__ void xproj_reduce_kernel() {
    int i = blockIdx.x * blockDim.x + threadIdx.x;
    if (i >= LSEQ * XDBL) return;
    float s = 0.f;
    #pragma unroll
    for (int z = 0; z < 8; z++) s += g_part[(size_t)z * LSEQ * XDBL + i];
    g_xdbl[i] = s;
    int l = i / XDBL, c = i - l * XDBL;
    if (c < 64) g_dt[(size_t)l * 64 + c] = __float2half(s);
}

// ---------------- fused residual-reduce + rmsnorm ----------------
__global__ void outred_rms_kernel(const float* __restrict__ norm_w,
                                  float* __restrict__ dest, int do_norm) {
    int l = blockIdx.x;
    float v[3];
    float s = 0.f;
    #pragma unroll
    for (int i = 0; i < 3; i++) {
        int d = threadIdx.x + i * 256;
        size_t idx = (size_t)l * DM + d;
        float t = g_x[idx];
        #pragma unroll
        for (int z = 0; z < 3; z++) t += g_part[(size_t)z * LSEQ * DM + idx];
        dest[idx] = t;
        v[i] = t;
        s += t * t;
    }
    if (!do_norm) return;
    __shared__ float red[8];
    #pragma unroll
    for (int o = 16; o; o >>= 1) s += __shfl_xor_sync(0xffffffffu, s, o);
    if ((threadIdx.x & 31) == 0) red[threadIdx.x >> 5] = s;
    __syncthreads();
    if (threadIdx.x < 8) {
        float t = red[threadIdx.x];
        #pragma unroll
        for (int o = 4; o; o >>= 1) t += __shfl_xor_sync(0xffu, t, o);
        if (threadIdx.x == 0) red[0] = rsqrtf(t / (float)DM + 1e-5f);
    }
    __syncthreads();
    float rinv = red[0];
    #pragma unroll
    for (int i = 0; i < 3; i++) {
        int d = threadIdx.x + i * 256;
        g_xn[(size_t)l * DM + d] = __float2half(v[i] * rinv * norm_w[d]);
    }
}

// ---------------- fused embed + rmsnorm ----------------
__global__ void embed_rms_kernel(const int* __restrict__ ids,
                                 const float* __restrict__ emb,
                                 const float* __restrict__ norm_w) {
    int l = blockIdx.x;
    const float* erow = emb + (size_t)ids[l] * DM;
    float v[3];
    float s = 0.f;
    #pragma unroll
    for (int i = 0; i < 3; i++) {
        int d = threadIdx.x + i * 256;
        float t = erow[d];
        g_x[(size_t)l * DM + d] = t;
        v[i] = t;
        s += t * t;
    }
    __shared__ float red[8];
    #pragma unroll
    for (int o = 16; o; o >>= 1) s += __shfl_xor_sync(0xffffffffu, s, o);
    if ((threadIdx.x & 31) == 0) red[threadIdx.x >> 5] = s;
    __syncthreads();
    if (threadIdx.x < 8) {
        float t = red[threadIdx.x];
        #pragma unroll
        for (int o = 4; o; o >>= 1) t += __shfl_xor_sync(0xffu, t, o);
        if (threadIdx.x == 0) red[0] = rsqrtf(t / (float)DM + 1e-5f);
    }
    __syncthreads();
    float rinv = red[0];
    #pragma unroll
    for (int i = 0; i < 3; i++) {
        int d = threadIdx.x + i * 256;
        g_xn[(size_t)l * DM + d] = __float2half(v[i] * rinv * norm_w[d]);
    }
}

// ---------------- fused weight prep (all transposes, both layers) ----------------
#define WP_TIN  2304
#define WP_TOUT 1152
#define WP_TXP  192
#define WP_TDT  96
#define WP_PER_LAYER (WP_TIN + WP_TOUT + WP_TXP + WP_TDT)

__device__ __forceinline__ void wp_tile(const float* __restrict__ W,
                                        __half* __restrict__ out,
                                        int Kin, int Kpad, int N, int Npad,
                                        int k0, int n0) {
    __shared__ float t[32][33];
    #pragma unroll
    for (int i = 0; i < 4; i++) {
        int k = k0 + threadIdx.y + i * 8;
        int n = n0 + threadIdx.x;
        t[threadIdx.y + i * 8][threadIdx.x] =
            (k < Kin && n < N) ? W[(size_t)k * N + n] : 0.f;
    }
    __syncthreads();
    #pragma unroll
    for (int i = 0; i < 4; i++) {
        int n = n0 + threadIdx.y + i * 8;
        int k = k0 + threadIdx.x;
        if (n < Npad && k < Kpad)
            out[(size_t)n * Kpad + k] = __float2half(t[threadIdx.x][threadIdx.y + i * 8]);
    }
}

__global__ void wprep_kernel(const float* __restrict__ in_proj_w,
                             const float* __restrict__ out_proj_w,
                             const float* __restrict__ x_proj_w,
                             const float* __restrict__ dt_proj_w) {
    int layer = blockIdx.y;
    int b = blockIdx.x;
    if (b < WP_TIN) {
        int kt = b % 24, nt = b / 24;
        wp_tile(in_proj_w + (size_t)layer * DM * DXZ,
                g_win + (size_t)layer * DM * DXZ,
                DM, DM, DXZ, DXZ, kt * 32, nt * 32);
        return;
    }
    b -= WP_TIN;
    if (b < WP_TOUT) {
        int kt = b % 48, nt = b / 48;
        wp_tile(out_proj_w + (size_t)layer * DI * DM,
                g_wout + (size_t)layer * DI * DM,
                DI, DI, DM, DM, kt * 32, nt * 32);
        return;
    }
    b -= WP_TOUT;
    if (b < WP_TXP) {
        int kt = b % 48, nt = b / 48;
        wp_tile(x_proj_w + (size_t)layer * DI * XDBL,
                g_wxp + (size_t)layer * 128 * DI,
                DI, DI, XDBL, 128, kt * 32, nt * 32);
        return;
    }
    b -= WP_TXP;
    {
        int kt = b % 2, nt = b / 2;
        wp_tile(dt_proj_w + (size_t)layer * DTR * DI,
                g_wdt + (size_t)layer * DI * 64,
                DTR, 64, DI, DI, kt * 32, nt * 32);
    }
}

// conv + silu: fp16 in (g_xzh), fp16 out (g_xrh), 8 outputs/thread
__global__ void conv_silu_kernel(const float* __restrict__ w,
                                 const float* __restrict__ b) {
    int d = blockIdx.x * 256 + threadIdx.x;
    int l0 = blockIdx.y * 8;
    float w0 = w[d * DCONV + 0], w1 = w[d * DCONV + 1];
    float w2 = w[d * DCONV + 2], w3 = w[d * DCONV + 3];
    float bb = b[d];
    float x[11];
    #pragma unroll
    for (int t = 0; t < 11; t++) {
        int ll = l0 - 3 + t;
        x[t] = (ll >= 0 && ll < LSEQ) ?
            __half2float(g_xzh[(size_t)ll * DI + d]) : 0.f;
    }
    #pragma unroll
    for (int j = 0; j < 8; j++) {
        float s = bb;
        s = fmaf(w0, x[j + 0], s);
        s = fmaf(w1, x[j + 1], s);
        s = fmaf(w2, x[j + 2], s);
        s = fmaf(w3, x[j + 3], s);
        float sig = 1.f / (1.f + __expf(-s));
        g_xrh[(size_t)(l0 + j) * DI + d] = __float2half(s * sig);
    }
}

// ---------------- fused selective scan: decoupled chain lookback ----------------
// grid (NDB, NCH) with chunk on blockIdx.y (slowest) so predecessor (same db,
// chunk-1) always has a lower linear block ID. 72KB dyn smem -> 3 CTAs/SM =
// 444 slots >= 384 blocks: all blocks co-resident, spin-wait is safe.
// Arithmetic is identical (same op order) to the previous 3-phase version.
#define SCAN_SMEM ((CLEN * DS * 2 + CLEN * 128 * 2) * 4)   // sB,sC + sDl,sU = 73728 B

__global__ void __launch_bounds__(128)
scan_fused_kernel(const float* __restrict__ A_log, const float* __restrict__ Dp,
                  int slot) {
    extern __shared__ float ssm[];
    float (*sB)[DS]   = reinterpret_cast<float(*)[DS]>(ssm);
    float (*sC)[DS]   = reinterpret_cast<float(*)[DS]>(ssm + CLEN * DS);
    float (*sDl)[128] = reinterpret_cast<float(*)[128]>(ssm + 2 * CLEN * DS);
    float (*sU)[128]  = reinterpret_cast<float(*)[128]>(ssm + 2 * CLEN * DS + CLEN * 128);

    const int db = blockIdx.x, chunk = blockIdx.y;
    const int d = db * 128 + threadIdx.x;
    const int l0 = chunk * CLEN;

    // clear the OTHER slot's flag entry for the next launch (stream-ordered safe)
    if (threadIdx.x == 0) g_flags[slot ^ 1][db * NCH + chunk] = 0;

    for (int idx = threadIdx.x; idx < CLEN * DS; idx += 128) {
        int l = idx >> 4, n = idx & 15;
        sB[l][n] = g_xdbl[(size_t)(l0 + l) * XDBL + DTR + n];
        sC[l][n] = g_xdbl[(size_t)(l0 + l) * XDBL + DTR + DS + n];
    }
    __syncthreads();

    float Arow[DS], h[DS], P[DS];
    bool chain = true;
    #pragma unroll
    for (int n = 0; n < DS; n++) {
        Arow[n] = -__expf(A_log[(size_t)d * DS + n]);
        h[n] = 0.f; P[n] = 1.f;
    }
    float r0 = Arow[0];
    #pragma unroll
    for (int n = 1; n < DS; n++)
        chain = chain && (fabsf(Arow[n] - (float)(n + 1) * r0)
                          <= 1e-5f * fabsf(Arow[n]) + 1e-7f);

    // ---- pass 1: local scan from zero; cache delta/u in smem ----
    if (chain) {
        for (int l = 0; l < CLEN; l++) {
            float dl = g_delta[(size_t)(l0 + l) * DI + d];
            float u  = __half2float(g_xrh[(size_t)(l0 + l) * DI + d]);
            sDl[l][threadIdx.x] = dl;
            sU [l][threadIdx.x] = u;
            float du = dl * u;
            float q = __expf(dl * r0);
            float a = 1.f;
            #pragma unroll
            for (int n = 0; n < DS; n++) {
                a *= q;
                h[n] = fmaf(a, h[n], du * sB[l][n]);
                P[n] *= a;
            }
        }
    } else {
        for (int l = 0; l < CLEN; l++) {
            float dl = g_delta[(size_t)(l0 + l) * DI + d];
            float u  = __half2float(g_xrh[(size_t)(l0 + l) * DI + d]);
            sDl[l][threadIdx.x] = dl;
            sU [l][threadIdx.x] = u;
            float du = dl * u;
            #pragma unroll
            for (int n = 0; n < DS; n++) {
                float a = __expf(dl * Arow[n]);
                h[n] = fmaf(a, h[n], du * sB[l][n]);
                P[n] *= a;
            }
        }
    }

    // ---- lookback: wait for predecessor's inclusive state ----
    float Hinit[DS];
    if (chunk == 0) {
        #pragma unroll
        for (int n = 0; n < DS; n++) Hinit[n] = 0.f;
    } else {
        if (threadIdx.x == 0) {
            volatile int* f = &g_flags[slot][db * NCH + chunk - 1];
            while (*f == 0) {}
        }
        __syncthreads();
        __threadfence();
        size_t pbase = ((size_t)(chunk - 1) * DI + d) * DS;
        #pragma unroll
        for (int n = 0; n < DS; n++) Hinit[n] = g_Hincl[pbase + n];
    }

    // ---- publish own inclusive state (skip for last chunk) ----
    if (chunk < NCH - 1) {
        size_t base = ((size_t)chunk * DI + d) * DS;
        #pragma unroll
        for (int n = 0; n < DS; n++)
            g_Hincl[base + n] = fmaf(P[n], Hinit[n], h[n]);
        __threadfence();
        __syncthreads();
        if (threadIdx.x == 0) g_flags[slot][db * NCH + chunk] = 1;
    }

    // ---- pass 2: rescan with correct Hinit, emit ya ----
    #pragma unroll
    for (int n = 0; n < DS; n++) h[n] = Hinit[n];
    float Dd = Dp[d];

    for (int l = 0; l < CLEN; l++) {
        float dl = sDl[l][threadIdx.x];
        float u  = sU [l][threadIdx.x];
        float du = dl * u;
        float y = 0.f;
        if (chain) {
            float q = __expf(dl * r0);
            float a = 1.f;
            #pragma unroll
            for (int n = 0; n < DS; n++) {
                a *= q;
                h[n] = fmaf(a, h[n], du * sB[l][n]);
                y = fmaf(h[n], sC[l][n], y);
            }
        } else {
            #pragma unroll
            for (int n = 0; n < DS; n++) {
                float a = __expf(dl * Arow[n]);
                h[n] = fmaf(a, h[n], du * sB[l][n]);
                y = fmaf(h[n], sC[l][n], y);
            }
        }
        y = fmaf(u, Dd, y);
        float res = g_res[(size_t)(l0 + l) * DI + d];
        float sig = 1.f / (1.f + __expf(-res));
        g_ya[(size_t)(l0 + l) * DI + d] = __float2half(y * (res * sig));
    }
}

// ---------------- launcher ----------------
extern "C" void kernel_launch(void* const* d_in, const int* in_sizes, int n_in,
                              void* d_out, int out_size) {
    const int*   ids        = (const int*)  d_in[0];
    const float* emb        = (const float*)d_in[1];
    const float* norm_w     = (const float*)d_in[2];
    const float* in_proj_w  = (const float*)d_in[3];
    const float* conv_w     = (const float*)d_in[4];
    const float* conv_b     = (const float*)d_in[5];
    const float* x_proj_w   = (const float*)d_in[6];
    const float* dt_proj_w  = (const float*)d_in[7];
    const float* dt_proj_b  = (const float*)d_in[8];
    const float* A_log      = (const float*)d_in[9];
    const float* Dp         = (const float*)d_in[10];
    const float* out_proj_w = (const float*)d_in[11];
    float* out = (float*)d_out;

    cudaFuncSetAttribute(gemm_fp16_kernel<2, 12>,
                         cudaFuncAttributeMaxDynamicSharedMemorySize, SMEM_MMA);
    cudaFuncSetAttribute(gemm_fp16_kernel<0, 3>,
                         cudaFuncAttributeMaxDynamicSharedMemorySize, SMEM_MMA);
    cudaFuncSetAttribute(gemm_fp16_kernel<1, 1>,
                         cudaFuncAttributeMaxDynamicSharedMemorySize, SMEM_MMA);
    cudaFuncSetAttribute(gemm_fp16_kernel<0, 8>,
                         cudaFuncAttributeMaxDynamicSharedMemorySize, SMEM_MMA);
    cudaFuncSetAttribute(scan_fused_kernel,
                         cudaFuncAttributeMaxDynamicSharedMemorySize, SCAN_SMEM);

    __half *xn, *xzh, *xrh, *ya, *dt, *win, *wout, *wxp, *wdt;
    float *res, *x_res, *part, *delta;
    cudaGetSymbolAddress((void**)&xn,    g_xn);
    cudaGetSymbolAddress((void**)&xzh,   g_xzh);
    cudaGetSymbolAddress((void**)&xrh,   g_xrh);
    cudaGetSymbolAddress((void**)&ya,    g_ya);
    cudaGetSymbolAddress((void**)&dt,    g_dt);
    cudaGetSymbolAddress((void**)&win,   g_win);
    cudaGetSymbolAddress((void**)&wout,  g_wout);
    cudaGetSymbolAddress((void**)&wxp,   g_wxp);
    cudaGetSymbolAddress((void**)&wdt,   g_wdt);
    cudaGetSymbolAddress((void**)&res,   g_res);
    cudaGetSymbolAddress((void**)&x_res, g_x);
    cudaGetSymbolAddress((void**)&part,  g_part);
    cudaGetSymbolAddress((void**)&delta, g_delta);

    wprep_kernel<<<dim3(WP_PER_LAYER, NLAYER), dim3(32, 8)>>>(
        in_proj_w, out_proj_w, x_proj_w, dt_proj_w);

    embed_rms_kernel<<<LSEQ, 256>>>(ids, emb, norm_w);

    for (int layer = 0; layer < NLAYER; layer++) {
        const __half* wt_in  = win  + (size_t)layer * DM * DXZ;
        const __half* wt_out = wout + (size_t)layer * DI * DM;
        const __half* wt_xp  = wxp  + (size_t)layer * 128 * DI;
        const __half* wt_dt  = wdt  + (size_t)layer * DI * 64;

        // in_proj: K=768 -> S=12 slabs; split write fp16-xr / fp32-res
        gemm_fp16_kernel<2, 12><<<dim3(DXZ / 128, LSEQ / 128, 1), 256, SMEM_MMA>>>(
            xn, wt_in, res, xzh, nullptr, DM, DXZ, DXZ);

        conv_silu_kernel<<<dim3(DI / 256, LSEQ / 8), 256>>>(
            conv_w + (size_t)layer * DI * DCONV,
            conv_b + (size_t)layer * DI);

        // x_proj: split-K 8 (S=3 slabs each, 8*192=1536) + reduce
        gemm_fp16_kernel<0, 3><<<dim3(1, LSEQ / 128, 8), 256, SMEM_MMA>>>(
            xrh, wt_xp, part, nullptr, nullptr, DI, XDBL, XDBL);
        xproj_reduce_kernel<<<(LSEQ * XDBL + 255) / 256, 256>>>();

        // dt_proj: K=64 -> S=1; softplus+bias epilogue
        gemm_fp16_kernel<1, 1><<<dim3(DI / 128, LSEQ / 128, 1), 256, SMEM_MMA>>>(
            dt, wt_dt, delta, nullptr, dt_proj_b + (size_t)layer * DI, 64, DI, DI);

        // fused scan (A+B+C in one kernel, decoupled chain lookback)
        scan_fused_kernel<<<dim3(NDB, NCH), 128, SCAN_SMEM>>>(
            A_log + (size_t)layer * DI * DS,
            Dp + (size_t)layer * DI, layer);

        // out_proj: split-K 3 (S=8 each, 3*512=1536) + fused reduce/rms
        gemm_fp16_kernel<0, 8><<<dim3(DM / 128, LSEQ / 128, 3), 256, SMEM_MMA>>>(
            ya, wt_out, part, nullptr, nullptr, DI, DM, DM);

        if (layer == NLAYER - 1) {
            outred_rms_kernel<<<LSEQ, 256>>>(nullptr, out, 0);
        } else {
            outred_rms_kernel<<<LSEQ, 256>>>(norm_w + (size_t)(layer + 1) * DM,
                                             x_res, 1);
        }
    }
}

// round 14
// speedup vs baseline: 1.0967x; 1.0967x over previous
#include <cuda_runtime.h>
#include <cuda_fp16.h>
#include <math.h>
#include <stdint.h>

// ---------------- problem constants ----------------
#define LSEQ   2048
#define DM     768
#define DI     1536          // 2*DM
#define DXZ    3072          // 2*DI
#define DTR    48
#define DS     16
#define DCONV  4
#define NLAYER 2
#define XDBL   80            // DTR + 2*DS
#define NCH    64
#define CLEN   32            // LSEQ / NCH

// ---------------- scratch (device globals, no allocation) ----------------
__device__ __align__(16) float g_x   [LSEQ * DM];    // residual stream
__device__ __align__(16) float g_xz  [LSEQ * DXZ];   // in_proj output (xr | res)
__device__ __align__(16) float g_xr  [LSEQ * DI];    // conv+silu output (fp32 for scan)
__device__ __align__(16) float g_xdbl[LSEQ * XDBL];  // x_proj output (dt | B | C)
__device__ __align__(16) float g_delta[LSEQ * DI];   // softplus(dt@dt_proj + b)
__device__ __align__(16) float g_Aprod[NCH * DI * DS];
__device__ __align__(16) float g_Hend [NCH * DI * DS];
__device__ __align__(16) float g_Hinit[NCH * DI * DS];

// fp16 activations for tensor-core GEMMs
__device__ __align__(16) __half g_xn [LSEQ * DM];
__device__ __align__(16) __half g_xrh[LSEQ * DI];
__device__ __align__(16) __half g_ya [LSEQ * DI];
__device__ __align__(16) __half g_dt [LSEQ * 64];     // dt cols padded 48->64
// fp16 weights, transposed [N][K], per-layer buffers (prepared once at start)
__device__ __align__(16) __half g_win [NLAYER * DM * DXZ];
__device__ __align__(16) __half g_wout[NLAYER * DI * DM];
__device__ __align__(16) __half g_wxp [NLAYER * 128 * DI];
__device__ __align__(16) __half g_wdt [NLAYER * DI * 64];
// split-K partials
__device__ __align__(16) float g_part[3 * LSEQ * DM];

// ---------------- small helpers ----------------
__device__ __forceinline__ uint32_t smem_u32(const void* p) {
    uint32_t a;
    asm("{ .reg .u64 t; cvta.to.shared.u64 t, %1; cvt.u32.u64 %0, t; }"
        : "=r"(a) : "l"(p));
    return a;
}
__device__ __forceinline__ void ldm4(uint32_t addr, uint32_t r[4]) {
    asm volatile("ldmatrix.sync.aligned.m8n8.x4.shared.b16 {%0,%1,%2,%3}, [%4];"
                 : "=r"(r[0]), "=r"(r[1]), "=r"(r[2]), "=r"(r[3]) : "r"(addr));
}
__device__ __forceinline__ void mma16816(float c[4], const uint32_t a[4],
                                         const uint32_t b0, const uint32_t b1) {
    asm volatile(
        "mma.sync.aligned.m16n8k16.row.col.f32.f16.f16.f32 "
        "{%0,%1,%2,%3}, {%4,%5,%6,%7}, {%8,%9}, {%0,%1,%2,%3};"
        : "+f"(c[0]), "+f"(c[1]), "+f"(c[2]), "+f"(c[3])
        : "r"(a[0]), "r"(a[1]), "r"(a[2]), "r"(a[3]), "r"(b0), "r"(b1));
}

// ---------------- single-term fp16 GEMM via mma.sync, templated M-tile ----------------
// C[2048,N] = A[2048,K] @ B^T with B as [N][K] row-major fp16.
// Tile MROWSx128, K-slab 64, 3 stages, 2 CTAs/SM, fragment-first mainloop.
// 8 warps arranged as NMW m-warps x (8/NMW) n-warps; each n-warp covers
// NG = NMW groups of 16 columns (M128: 4m x 2n, 64 cols/warp; M64: 2m x 4n, 32 cols/warp).
#define SROW    72                       // 64 halfs + 8 pad
#define NSTAGE  3
#define TILE_B_E (128 * SROW)

template<int MROWS>
__device__ __forceinline__ void mma_load_stage(
        uint32_t smb, int stage,
        const __half* __restrict__ A, const __half* __restrict__ B,
        int row0, int col0, int k0, int K, int tid) {
    constexpr int TA = MROWS * SROW;
    constexpr int ST = TA + TILE_B_E;
    #pragma unroll
    for (int i = 0; i < MROWS / 32; i++) {
        int c = tid + i * 256;
        int row = c >> 3, kc = (c & 7) * 8;
        uint32_t dst = smb + (uint32_t)(stage * ST + row * SROW + kc) * 2u;
        const void* gsrc = A + (size_t)(row0 + row) * K + k0 + kc;
        asm volatile("cp.async.cg.shared.global [%0], [%1], 16;"
                     :: "r"(dst), "l"(gsrc));
    }
    #pragma unroll
    for (int i = 0; i < 4; i++) {
        int c = tid + i * 256;
        int row = c >> 3, kc = (c & 7) * 8;
        uint32_t dst = smb + (uint32_t)(stage * ST + TA + row * SROW + kc) * 2u;
        const void* gsrc = B + (size_t)(col0 + row) * K + k0 + kc;
        asm volatile("cp.async.cg.shared.global [%0], [%1], 16;"
                     :: "r"(dst), "l"(gsrc));
    }
    asm volatile("cp.async.commit_group;" ::: "memory");
}

// MODE 0: plain fp32 write   MODE 1: softplus(v + bias[n])
template<int MODE, int MROWS>
__global__ void __launch_bounds__(256, 2)
gemm_fp16_kernel(const __half* __restrict__ Ag, const __half* __restrict__ Bg,
                 float* __restrict__ C, const float* __restrict__ bias,
                 int K, int ksize, int ldc, int Nvalid) {
    extern __shared__ __half sm[];
    constexpr int NMW = MROWS / 32;          // m-warps (4 or 2)
    constexpr int NG  = NMW;                 // 16-col groups per n-warp (4 or 2)
    constexpr int TA  = MROWS * SROW;
    constexpr int ST  = TA + TILE_B_E;
    const int tid = threadIdx.x, lane = tid & 31, wid = tid >> 5;
    const int wm = wid % NMW, wn = wid / NMW;
    const int row0 = blockIdx.y * MROWS, col0 = blockIdx.x * 128;
    const int kb = blockIdx.z * ksize;
    C += (size_t)blockIdx.z * LSEQ * ldc;
    uint32_t smb = smem_u32(sm);

    float acc[2][2 * NG][4] = {};
    const int S = ksize / 64;

    mma_load_stage<MROWS>(smb, 0, Ag, Bg, row0, col0, kb, K, tid);
    if (S > 1) mma_load_stage<MROWS>(smb, 1, Ag, Bg, row0, col0, kb + 64, K, tid);

    const int lrow = lane & 15, lcol0 = (lane >> 4) * 8;

    for (int s = 0; s < S; s++) {
        if (s + 1 < S) {
            asm volatile("cp.async.wait_group 1;" ::: "memory");
        } else {
            asm volatile("cp.async.wait_group 0;" ::: "memory");
        }
        __syncthreads();
        if (s + 2 < S)
            mma_load_stage<MROWS>(smb, (s + 2) % NSTAGE, Ag, Bg,
                                  row0, col0, kb + (s + 2) * 64, K, tid);

        int st = s % NSTAGE;
        uint32_t bA = smb + (uint32_t)(st * ST) * 2u;
        uint32_t bB = smb + (uint32_t)(st * ST + TA) * 2u;

        #pragma unroll
        for (int kh = 0; kh < 64; kh += 32) {
            // fragment-first per 32-K half
            uint32_t ah[2][2][4];        // [kk2][mt]
            uint32_t bb[2][NG][4];       // [kk2][g]
            #pragma unroll
            for (int kk2 = 0; kk2 < 2; kk2++) {
                int kk = kh + kk2 * 16;
                #pragma unroll
                for (int mt = 0; mt < 2; mt++) {
                    uint32_t off = (uint32_t)((wm * 32 + mt * 16 + lrow) * SROW + kk + lcol0) * 2u;
                    ldm4(bA + off, ah[kk2][mt]);
                }
                #pragma unroll
                for (int g = 0; g < NG; g++) {
                    uint32_t off = (uint32_t)((wn * NG * 16 + g * 16 + lrow) * SROW + kk + lcol0) * 2u;
                    ldm4(bB + off, bb[kk2][g]);
                }
            }
            #pragma unroll
            for (int kk2 = 0; kk2 < 2; kk2++) {
                #pragma unroll
                for (int g = 0; g < NG; g++) {
                    #pragma unroll
                    for (int mt = 0; mt < 2; mt++) {
                        mma16816(acc[mt][2 * g + 0], ah[kk2][mt], bb[kk2][g][0], bb[kk2][g][2]);
                        mma16816(acc[mt][2 * g + 1], ah[kk2][mt], bb[kk2][g][1], bb[kk2][g][3]);
                    }
                }
            }
        }
    }

    // epilogue
    int gq = lane >> 2, tq = lane & 3;
    #pragma unroll
    for (int mt = 0; mt < 2; mt++) {
        #pragma unroll
        for (int n8 = 0; n8 < 2 * NG; n8++) {
            int rm = row0 + wm * 32 + mt * 16 + gq;
            int cn = col0 + wn * NG * 16 + n8 * 8 + 2 * tq;
            if (cn >= Nvalid) continue;
            float v[4] = {acc[mt][n8][0], acc[mt][n8][1],
                          acc[mt][n8][2], acc[mt][n8][3]};
            if (MODE == 1) {
                float b0 = bias[cn], b1 = bias[cn + 1];
                v[0] += b0; v[1] += b1; v[2] += b0; v[3] += b1;
                #pragma unroll
                for (int q = 0; q < 4; q++)
                    v[q] = (v[q] > 20.f) ? v[q] : log1pf(__expf(v[q]));
            }
            *reinterpret_cast<float2*>(C + (size_t)rm * ldc + cn) =
                make_float2(v[0], v[1]);
            *reinterpret_cast<float2*>(C + (size_t)(rm + 8) * ldc + cn) =
                make_float2(v[2], v[3]);
        }
    }
}

#define SMEM_M128 (NSTAGE * (128 * SROW + TILE_B_E) * 2)   // 110592 B
#define SMEM_M64  (NSTAGE * ( 64 * SROW + TILE_B_E) * 2)   //  82944 B

// reduce 8 x_proj split-K partials -> g_xdbl, emit fp16 dt cols (pad 64)
__global__ void xproj_reduce_kernel() {
    int i = blockIdx.x * blockDim.x + threadIdx.x;
    if (i >= LSEQ * XDBL) return;
    float s = 0.f;
    #pragma unroll
    for (int z = 0; z < 8; z++) s += g_part[(size_t)z * LSEQ * XDBL + i];
    g_xdbl[i] = s;
    int l = i / XDBL, c = i - l * XDBL;
    if (c < 64) g_dt[(size_t)l * 64 + c] = __float2half(s);
}

// ---------------- fused residual-reduce + rmsnorm ----------------
__global__ void outred_rms_kernel(const float* __restrict__ norm_w,
                                  float* __restrict__ dest, int do_norm) {
    int l = blockIdx.x;
    float v[3];
    float s = 0.f;
    #pragma unroll
    for (int i = 0; i < 3; i++) {
        int d = threadIdx.x + i * 256;
        size_t idx = (size_t)l * DM + d;
        float t = g_x[idx];
        #pragma unroll
        for (int z = 0; z < 3; z++) t += g_part[(size_t)z * LSEQ * DM + idx];
        dest[idx] = t;
        v[i] = t;
        s += t * t;
    }
    if (!do_norm) return;
    __shared__ float red[8];
    #pragma unroll
    for (int o = 16; o; o >>= 1) s += __shfl_xor_sync(0xffffffffu, s, o);
    if ((threadIdx.x & 31) == 0) red[threadIdx.x >> 5] = s;
    __syncthreads();
    if (threadIdx.x < 8) {
        float t = red[threadIdx.x];
        #pragma unroll
        for (int o = 4; o; o >>= 1) t += __shfl_xor_sync(0xffu, t, o);
        if (threadIdx.x == 0) red[0] = rsqrtf(t / (float)DM + 1e-5f);
    }
    __syncthreads();
    float rinv = red[0];
    #pragma unroll
    for (int i = 0; i < 3; i++) {
        int d = threadIdx.x + i * 256;
        g_xn[(size_t)l * DM + d] = __float2half(v[i] * rinv * norm_w[d]);
    }
}

// ---------------- fused embed + rmsnorm (layer 0 entry) ----------------
__global__ void embed_rms_kernel(const int* __restrict__ ids,
                                 const float* __restrict__ emb,
                                 const float* __restrict__ norm_w) {
    int l = blockIdx.x;
    const float* erow = emb + (size_t)ids[l] * DM;
    float v[3];
    float s = 0.f;
    #pragma unroll
    for (int i = 0; i < 3; i++) {
        int d = threadIdx.x + i * 256;
        float t = erow[d];
        g_x[(size_t)l * DM + d] = t;
        v[i] = t;
        s += t * t;
    }
    __shared__ float red[8];
    #pragma unroll
    for (int o = 16; o; o >>= 1) s += __shfl_xor_sync(0xffffffffu, s, o);
    if ((threadIdx.x & 31) == 0) red[threadIdx.x >> 5] = s;
    __syncthreads();
    if (threadIdx.x < 8) {
        float t = red[threadIdx.x];
        #pragma unroll
        for (int o = 4; o; o >>= 1) t += __shfl_xor_sync(0xffu, t, o);
        if (threadIdx.x == 0) red[0] = rsqrtf(t / (float)DM + 1e-5f);
    }
    __syncthreads();
    float rinv = red[0];
    #pragma unroll
    for (int i = 0; i < 3; i++) {
        int d = threadIdx.x + i * 256;
        g_xn[(size_t)l * DM + d] = __float2half(v[i] * rinv * norm_w[d]);
    }
}

// ---------------- fused weight prep (all transposes, both layers) ----------------
#define WP_TIN  2304
#define WP_TOUT 1152
#define WP_TXP  192
#define WP_TDT  96
#define WP_PER_LAYER (WP_TIN + WP_TOUT + WP_TXP + WP_TDT)

__device__ __forceinline__ void wp_tile(const float* __restrict__ W,
                                        __half* __restrict__ out,
                                        int Kin, int Kpad, int N, int Npad,
                                        int k0, int n0) {
    __shared__ float t[32][33];
    #pragma unroll
    for (int i = 0; i < 4; i++) {
        int k = k0 + threadIdx.y + i * 8;
        int n = n0 + threadIdx.x;
        t[threadIdx.y + i * 8][threadIdx.x] =
            (k < Kin && n < N) ? W[(size_t)k * N + n] : 0.f;
    }
    __syncthreads();
    #pragma unroll
    for (int i = 0; i < 4; i++) {
        int n = n0 + threadIdx.y + i * 8;
        int k = k0 + threadIdx.x;
        if (n < Npad && k < Kpad)
            out[(size_t)n * Kpad + k] = __float2half(t[threadIdx.x][threadIdx.y + i * 8]);
    }
}

__global__ void wprep_kernel(const float* __restrict__ in_proj_w,
                             const float* __restrict__ out_proj_w,
                             const float* __restrict__ x_proj_w,
                             const float* __restrict__ dt_proj_w) {
    int layer = blockIdx.y;
    int b = blockIdx.x;
    if (b < WP_TIN) {
        int kt = b % 24, nt = b / 24;
        wp_tile(in_proj_w + (size_t)layer * DM * DXZ,
                g_win + (size_t)layer * DM * DXZ,
                DM, DM, DXZ, DXZ, kt * 32, nt * 32);
        return;
    }
    b -= WP_TIN;
    if (b < WP_TOUT) {
        int kt = b % 48, nt = b / 48;
        wp_tile(out_proj_w + (size_t)layer * DI * DM,
                g_wout + (size_t)layer * DI * DM,
                DI, DI, DM, DM, kt * 32, nt * 32);
        return;
    }
    b -= WP_TOUT;
    if (b < WP_TXP) {
        int kt = b % 48, nt = b / 48;
        wp_tile(x_proj_w + (size_t)layer * DI * XDBL,
                g_wxp + (size_t)layer * 128 * DI,
                DI, DI, XDBL, 128, kt * 32, nt * 32);
        return;
    }
    b -= WP_TXP;
    {
        int kt = b % 2, nt = b / 2;
        wp_tile(dt_proj_w + (size_t)layer * DTR * DI,
                g_wdt + (size_t)layer * DI * 64,
                DTR, 64, DI, DI, kt * 32, nt * 32);
    }
}

// conv + silu: 8 outputs along l per thread, taps reused in registers
__global__ void conv_silu_kernel(const float* __restrict__ w,
                                 const float* __restrict__ b) {
    int d = blockIdx.x * 256 + threadIdx.x;
    int l0 = blockIdx.y * 8;
    float w0 = w[d * DCONV + 0], w1 = w[d * DCONV + 1];
    float w2 = w[d * DCONV + 2], w3 = w[d * DCONV + 3];
    float bb = b[d];
    float x[11];
    #pragma unroll
    for (int t = 0; t < 11; t++) {
        int ll = l0 - 3 + t;
        x[t] = (ll >= 0 && ll < LSEQ) ? g_xz[(size_t)ll * DXZ + d] : 0.f;
    }
    #pragma unroll
    for (int j = 0; j < 8; j++) {
        float s = bb;
        s = fmaf(w0, x[j + 0], s);
        s = fmaf(w1, x[j + 1], s);
        s = fmaf(w2, x[j + 2], s);
        s = fmaf(w3, x[j + 3], s);
        float sig = 1.f / (1.f + __expf(-s));
        float v = s * sig;
        size_t idx = (size_t)(l0 + j) * DI + d;
        g_xr[idx] = v;
        g_xrh[idx] = __float2half(v);
    }
}

// ---------------- chunked selective scan (power-chain exp) ----------------
__global__ void scan_phaseA_kernel(const float* __restrict__ A_log) {
    int d = blockIdx.x * blockDim.x + threadIdx.x;
    int chunk = blockIdx.y;
    __shared__ float sB[CLEN][DS];
    int l0 = chunk * CLEN;
    for (int idx = threadIdx.x; idx < CLEN * DS; idx += blockDim.x) {
        int l = idx >> 4, n = idx & 15;
        sB[l][n] = g_xdbl[(size_t)(l0 + l) * XDBL + DTR + n];
    }
    __syncthreads();

    float Arow[DS], h[DS], P[DS];
    bool chain = true;
    #pragma unroll
    for (int n = 0; n < DS; n++) {
        Arow[n] = -__expf(A_log[(size_t)d * DS + n]);
        h[n] = 0.f; P[n] = 1.f;
    }
    float r0 = Arow[0];
    #pragma unroll
    for (int n = 1; n < DS; n++)
        chain = chain && (fabsf(Arow[n] - (float)(n + 1) * r0)
                          <= 1e-5f * fabsf(Arow[n]) + 1e-7f);

    if (chain) {
        for (int l = 0; l < CLEN; l++) {
            float dl = g_delta[(size_t)(l0 + l) * DI + d];
            float du = dl * g_xr[(size_t)(l0 + l) * DI + d];
            float q = __expf(dl * r0);
            float a = 1.f;
            #pragma unroll
            for (int n = 0; n < DS; n++) {
                a *= q;
                h[n] = fmaf(a, h[n], du * sB[l][n]);
                P[n] *= a;
            }
        }
    } else {
        for (int l = 0; l < CLEN; l++) {
            float dl = g_delta[(size_t)(l0 + l) * DI + d];
            float du = dl * g_xr[(size_t)(l0 + l) * DI + d];
            #pragma unroll
            for (int n = 0; n < DS; n++) {
                float a = __expf(dl * Arow[n]);
                h[n] = fmaf(a, h[n], du * sB[l][n]);
                P[n] *= a;
            }
        }
    }
    size_t base = ((size_t)chunk * DI + d) * DS;
    #pragma unroll
    for (int n = 0; n < DS; n++) {
        g_Aprod[base + n] = P[n];
        g_Hend [base + n] = h[n];
    }
}

__global__ void scan_phaseB_kernel() {
    int i = blockIdx.x * blockDim.x + threadIdx.x;
    if (i >= DI * DS) return;
    float run = 0.f;
    #pragma unroll 8
    for (int c = 0; c < NCH; c++) {
        size_t idx = (size_t)c * DI * DS + i;
        g_Hinit[idx] = run;
        run = fmaf(g_Aprod[idx], run, g_Hend[idx]);
    }
}

__global__ void scan_phaseC_kernel(const float* __restrict__ A_log,
                                   const float* __restrict__ Dp) {
    int d = blockIdx.x * blockDim.x + threadIdx.x;
    int chunk = blockIdx.y;
    __shared__ float sB[CLEN][DS];
    __shared__ float sC[CLEN][DS];
    int l0 = chunk * CLEN;
    for (int idx = threadIdx.x; idx < CLEN * DS; idx += blockDim.x) {
        int l = idx >> 4, n = idx & 15;
        sB[l][n] = g_xdbl[(size_t)(l0 + l) * XDBL + DTR + n];
        sC[l][n] = g_xdbl[(size_t)(l0 + l) * XDBL + DTR + DS + n];
    }
    __syncthreads();

    float Arow[DS], h[DS];
    bool chain = true;
    size_t base = ((size_t)chunk * DI + d) * DS;
    #pragma unroll
    for (int n = 0; n < DS; n++) {
        Arow[n] = -__expf(A_log[(size_t)d * DS + n]);
        h[n] = g_Hinit[base + n];
    }
    float r0 = Arow[0];
    #pragma unroll
    for (int n = 1; n < DS; n++)
        chain = chain && (fabsf(Arow[n] - (float)(n + 1) * r0)
                          <= 1e-5f * fabsf(Arow[n]) + 1e-7f);
    float Dd = Dp[d];

    for (int l = 0; l < CLEN; l++) {
        float dl = g_delta[(size_t)(l0 + l) * DI + d];
        float u  = g_xr[(size_t)(l0 + l) * DI + d];
        float du = dl * u;
        float y = 0.f;
        if (chain) {
            float q = __expf(dl * r0);
            float a = 1.f;
            #pragma unroll
            for (int n = 0; n < DS; n++) {
                a *= q;
                h[n] = fmaf(a, h[n], du * sB[l][n]);
                y = fmaf(h[n], sC[l][n], y);
            }
        } else {
            #pragma unroll
            for (int n = 0; n < DS; n++) {
                float a = __expf(dl * Arow[n]);
                h[n] = fmaf(a, h[n], du * sB[l][n]);
                y = fmaf(h[n], sC[l][n], y);
            }
        }
        y = fmaf(u, Dd, y);
        float res = g_xz[(size_t)(l0 + l) * DXZ + DI + d];
        float sig = 1.f / (1.f + __expf(-res));
        g_ya[(size_t)(l0 + l) * DI + d] = __float2half(y * (res * sig));
    }
}

// ---------------- launcher ----------------
extern "C" void kernel_launch(void* const* d_in, const int* in_sizes, int n_in,
                              void* d_out, int out_size) {
    const int*   ids        = (const int*)  d_in[0];
    const float* emb        = (const float*)d_in[1];
    const float* norm_w     = (const float*)d_in[2];
    const float* in_proj_w  = (const float*)d_in[3];
    const float* conv_w     = (const float*)d_in[4];
    const float* conv_b     = (const float*)d_in[5];
    const float* x_proj_w   = (const float*)d_in[6];
    const float* dt_proj_w  = (const float*)d_in[7];
    const float* dt_proj_b  = (const float*)d_in[8];
    const float* A_log      = (const float*)d_in[9];
    const float* Dp         = (const float*)d_in[10];
    const float* out_proj_w = (const float*)d_in[11];
    float* out = (float*)d_out;

    cudaFuncSetAttribute(gemm_fp16_kernel<0, 64>,
                         cudaFuncAttributeMaxDynamicSharedMemorySize, SMEM_M64);
    cudaFuncSetAttribute(gemm_fp16_kernel<0, 128>,
                         cudaFuncAttributeMaxDynamicSharedMemorySize, SMEM_M128);
    cudaFuncSetAttribute(gemm_fp16_kernel<1, 128>,
                         cudaFuncAttributeMaxDynamicSharedMemorySize, SMEM_M128);

    __half *xn, *xrh, *ya, *dt, *win, *wout, *wxp, *wdt;
    float *xz, *x_res, *part, *delta;
    cudaGetSymbolAddress((void**)&xn,    g_xn);
    cudaGetSymbolAddress((void**)&xrh,   g_xrh);
    cudaGetSymbolAddress((void**)&ya,    g_ya);
    cudaGetSymbolAddress((void**)&dt,    g_dt);
    cudaGetSymbolAddress((void**)&win,   g_win);
    cudaGetSymbolAddress((void**)&wout,  g_wout);
    cudaGetSymbolAddress((void**)&wxp,   g_wxp);
    cudaGetSymbolAddress((void**)&wdt,   g_wdt);
    cudaGetSymbolAddress((void**)&xz,    g_xz);
    cudaGetSymbolAddress((void**)&x_res, g_x);
    cudaGetSymbolAddress((void**)&part,  g_part);
    cudaGetSymbolAddress((void**)&delta, g_delta);

    wprep_kernel<<<dim3(WP_PER_LAYER, NLAYER), dim3(32, 8)>>>(
        in_proj_w, out_proj_w, x_proj_w, dt_proj_w);

    embed_rms_kernel<<<LSEQ, 256>>>(ids, emb, norm_w);

    for (int layer = 0; layer < NLAYER; layer++) {
        const __half* wt_in  = win  + (size_t)layer * DM * DXZ;
        const __half* wt_out = wout + (size_t)layer * DI * DM;
        const __half* wt_xp  = wxp  + (size_t)layer * 128 * DI;
        const __half* wt_dt  = wdt  + (size_t)layer * DI * 64;

        // in_proj: M-tile 64 -> 768 half-size CTAs, no wave-quantization waste
        gemm_fp16_kernel<0, 64><<<dim3(DXZ / 128, LSEQ / 64, 1), 256, SMEM_M64>>>(
            xn, wt_in, xz, nullptr, DM, DM, DXZ, DXZ);

        conv_silu_kernel<<<dim3(DI / 256, LSEQ / 8), 256>>>(
            conv_w + (size_t)layer * DI * DCONV,
            conv_b + (size_t)layer * DI);

        // x_proj: split-K 8 (ksize 192) + reduce
        gemm_fp16_kernel<0, 128><<<dim3(1, LSEQ / 128, 8), 256, SMEM_M128>>>(
            xrh, wt_xp, part, nullptr, DI, DI / 8, XDBL, XDBL);
        xproj_reduce_kernel<<<(LSEQ * XDBL + 255) / 256, 256>>>();

        // dt_proj: K=64, softplus+bias epilogue
        gemm_fp16_kernel<1, 128><<<dim3(DI / 128, LSEQ / 128, 1), 256, SMEM_M128>>>(
            dt, wt_dt, delta, dt_proj_b + (size_t)layer * DI, 64, 64, DI, DI);

        scan_phaseA_kernel<<<dim3(DI / 128, NCH), 128>>>(
            A_log + (size_t)layer * DI * DS);
        scan_phaseB_kernel<<<(DI * DS + 255) / 256, 256>>>();
        scan_phaseC_kernel<<<dim3(DI / 128, NCH), 128>>>(
            A_log + (size_t)layer * DI * DS,
            Dp + (size_t)layer * DI);

        // out_proj: split-K 3 + fused reduce/rms
        gemm_fp16_kernel<0, 128><<<dim3(DM / 128, LSEQ / 128, 3), 256, SMEM_M128>>>(
            ya, wt_out, part, nullptr, DI, DI / 3, DM, DM);

        if (layer == NLAYER - 1) {
            outred_rms_kernel<<<LSEQ, 256>>>(nullptr, out, 0);
        } else {
            outred_rms_kernel<<<LSEQ, 256>>>(norm_w + (size_t)(layer + 1) * DM,
                                             x_res, 1);
        }
    }
}

// round 15
// speedup vs baseline: 1.1297x; 1.0301x over previous
#include <cuda_runtime.h>
#include <cuda_fp16.h>
#include <math.h>
#include <stdint.h>

// ---------------- problem constants ----------------
#define LSEQ   2048
#define DM     768
#define DI     1536          // 2*DM
#define DXZ    3072          // 2*DI
#define DTR    48
#define DS     16
#define DCONV  4
#define NLAYER 2
#define XDBL   80            // DTR + 2*DS
#define NCH    64
#define CLEN   32            // LSEQ / NCH

// ---------------- scratch (device globals, no allocation) ----------------
__device__ __align__(16) float g_x   [LSEQ * DM];    // residual stream
__device__ __align__(16) float g_xz  [LSEQ * DXZ];   // in_proj output (xr | res)
__device__ __align__(16) float g_xr  [LSEQ * DI];    // conv+silu output (fp32 for scan)
__device__ __align__(16) float g_delta[LSEQ * DI];   // softplus(dt@dt_proj + b)
__device__ __align__(16) float g_Aprod[NCH * DI * DS];
__device__ __align__(16) float g_Hend [NCH * DI * DS];
__device__ __align__(16) float g_Hinit[NCH * DI * DS];

// fp16 activations for tensor-core GEMMs
__device__ __align__(16) __half g_xn [LSEQ * DM];
__device__ __align__(16) __half g_xrh[LSEQ * DI];
__device__ __align__(16) __half g_ya [LSEQ * DI];
// fp16 weights, transposed [N][K], per-layer buffers (prepared once at start)
__device__ __align__(16) __half g_win [NLAYER * DM * DXZ];
__device__ __align__(16) __half g_wout[NLAYER * DI * DM];
__device__ __align__(16) __half g_wxp [NLAYER * 128 * DI];
__device__ __align__(16) __half g_wdt [NLAYER * DI * 64];
// split-K partials (x_proj: 8 x 2048 x 80; out_proj: 3 x 2048 x 768)
__device__ __align__(16) float g_part[3 * LSEQ * DM];

// ---------------- small helpers ----------------
__device__ __forceinline__ uint32_t smem_u32(const void* p) {
    uint32_t a;
    asm("{ .reg .u64 t; cvta.to.shared.u64 t, %1; cvt.u32.u64 %0, t; }"
        : "=r"(a) : "l"(p));
    return a;
}
__device__ __forceinline__ void ldm4(uint32_t addr, uint32_t r[4]) {
    asm volatile("ldmatrix.sync.aligned.m8n8.x4.shared.b16 {%0,%1,%2,%3}, [%4];"
                 : "=r"(r[0]), "=r"(r[1]), "=r"(r[2]), "=r"(r[3]) : "r"(addr));
}
__device__ __forceinline__ void mma16816(float c[4], const uint32_t a[4],
                                         const uint32_t b0, const uint32_t b1) {
    asm volatile(
        "mma.sync.aligned.m16n8k16.row.col.f32.f16.f16.f32 "
        "{%0,%1,%2,%3}, {%4,%5,%6,%7}, {%8,%9}, {%0,%1,%2,%3};"
        : "+f"(c[0]), "+f"(c[1]), "+f"(c[2]), "+f"(c[3])
        : "r"(a[0]), "r"(a[1]), "r"(a[2]), "r"(a[3]), "r"(b0), "r"(b1));
}

// ---------------- single-term fp16 GEMM via mma.sync ----------------
// C[2048,N] = A[2048,K] @ B^T with B as [N][K] row-major fp16.
// Tile 128x128, K-slab 64, 3 stages, 2 CTAs/SM, fragment-first mainloop.
#define SROW    72                       // 64 halfs + 8 pad
#define NSTAGE  3
#define TILE_E  (128 * SROW)
#define SMEM_MMA (NSTAGE * 2 * TILE_E * 2)   // 110592 B

__device__ __forceinline__ void mma_load_stage(
        uint32_t smb, int stage,
        const __half* __restrict__ A, const __half* __restrict__ B,
        int row0, int col0, int k0, int K, int tid) {
    #pragma unroll
    for (int t = 0; t < 2; t++) {
        const __half* src = (t == 0) ? A : B;
        int r0 = (t == 0) ? row0 : col0;
        #pragma unroll
        for (int i = 0; i < 4; i++) {
            int c = tid + i * 256;
            int row = c >> 3, kc = (c & 7) * 8;
            uint32_t dst = smb + (uint32_t)(((stage * 2 + t) * TILE_E) + row * SROW + kc) * 2u;
            const void* gsrc = src + (size_t)(r0 + row) * K + k0 + kc;
            asm volatile("cp.async.cg.shared.global [%0], [%1], 16;"
                         :: "r"(dst), "l"(gsrc));
        }
    }
    asm volatile("cp.async.commit_group;" ::: "memory");
}

// MODE 0: plain fp32 write
__global__ void __launch_bounds__(256, 2)
gemm_fp16_kernel(const __half* __restrict__ Ag, const __half* __restrict__ Bg,
                 float* __restrict__ C, int K, int ksize, int ldc, int Nvalid) {
    extern __shared__ __half sm[];
    const int tid = threadIdx.x, lane = tid & 31, wid = tid >> 5;
    const int wm = wid & 3, wn = wid >> 2;
    const int row0 = blockIdx.y * 128, col0 = blockIdx.x * 128;
    const int kb = blockIdx.z * ksize;
    C += (size_t)blockIdx.z * LSEQ * ldc;
    uint32_t smb = smem_u32(sm);

    float acc[2][8][4] = {};
    const int S = ksize / 64;

    mma_load_stage(smb, 0, Ag, Bg, row0, col0, kb, K, tid);
    if (S > 1) mma_load_stage(smb, 1, Ag, Bg, row0, col0, kb + 64, K, tid);

    const int lrow = lane & 15, lcol0 = (lane >> 4) * 8;

    for (int s = 0; s < S; s++) {
        if (s + 1 < S) {
            asm volatile("cp.async.wait_group 1;" ::: "memory");
        } else {
            asm volatile("cp.async.wait_group 0;" ::: "memory");
        }
        __syncthreads();
        if (s + 2 < S)
            mma_load_stage(smb, (s + 2) % NSTAGE, Ag, Bg,
                           row0, col0, kb + (s + 2) * 64, K, tid);

        int st = s % NSTAGE;
        uint32_t bA = smb + (uint32_t)((st * 2 + 0) * TILE_E) * 2u;
        uint32_t bB = smb + (uint32_t)((st * 2 + 1) * TILE_E) * 2u;

        #pragma unroll
        for (int kh = 0; kh < 64; kh += 32) {
            uint32_t ah[2][2][4];
            uint32_t bb[2][4][4];
            #pragma unroll
            for (int kk2 = 0; kk2 < 2; kk2++) {
                int kk = kh + kk2 * 16;
                #pragma unroll
                for (int mt = 0; mt < 2; mt++) {
                    uint32_t off = (uint32_t)((wm * 32 + mt * 16 + lrow) * SROW + kk + lcol0) * 2u;
                    ldm4(bA + off, ah[kk2][mt]);
                }
                #pragma unroll
                for (int g = 0; g < 4; g++) {
                    uint32_t off = (uint32_t)((wn * 64 + g * 16 + lrow) * SROW + kk + lcol0) * 2u;
                    ldm4(bB + off, bb[kk2][g]);
                }
            }
            #pragma unroll
            for (int kk2 = 0; kk2 < 2; kk2++) {
                #pragma unroll
                for (int g = 0; g < 4; g++) {
                    #pragma unroll
                    for (int mt = 0; mt < 2; mt++) {
                        mma16816(acc[mt][2 * g + 0], ah[kk2][mt], bb[kk2][g][0], bb[kk2][g][2]);
                        mma16816(acc[mt][2 * g + 1], ah[kk2][mt], bb[kk2][g][1], bb[kk2][g][3]);
                    }
                }
            }
        }
    }

    // epilogue
    int gq = lane >> 2, tq = lane & 3;
    #pragma unroll
    for (int mt = 0; mt < 2; mt++) {
        #pragma unroll
        for (int n8 = 0; n8 < 8; n8++) {
            int rm = row0 + wm * 32 + mt * 16 + gq;
            int cn = col0 + wn * 64 + n8 * 8 + 2 * tq;
            if (cn >= Nvalid) continue;
            *reinterpret_cast<float2*>(C + (size_t)rm * ldc + cn) =
                make_float2(acc[mt][n8][0], acc[mt][n8][1]);
            *reinterpret_cast<float2*>(C + (size_t)(rm + 8) * ldc + cn) =
                make_float2(acc[mt][n8][2], acc[mt][n8][3]);
        }
    }
}

// ---------------- fused dt_proj: A = sum of 8 x_proj partials, softplus epilogue ----------------
// delta[2048, DI] = softplus( (sum_z part_z)[2048, 0..63] @ wdt[DI][64]^T + bias )
#define SMEM_DT ((128 + 128) * SROW * 2)   // 36864 B

__global__ void __launch_bounds__(256, 2)
dtproj_kernel(const __half* __restrict__ Bg, float* __restrict__ C,
              const float* __restrict__ bias) {
    extern __shared__ __half sm[];
    constexpr int TA = 128 * SROW;
    const int tid = threadIdx.x, lane = tid & 31, wid = tid >> 5;
    const int wm = wid & 3, wn = wid >> 2;
    const int row0 = blockIdx.y * 128, col0 = blockIdx.x * 128;
    uint32_t smb = smem_u32(sm);

    // A tile: reduce 8 split-K partials (cols 0..63 of XDBL layout) -> fp16 smem
    #pragma unroll
    for (int i = 0; i < 32; i++) {
        int e = tid + i * 256;           // 0..8191
        int r = e >> 6, c = e & 63;
        size_t base = (size_t)(row0 + r) * XDBL + c;
        float s = 0.f;
        #pragma unroll
        for (int z = 0; z < 8; z++) s += g_part[(size_t)z * LSEQ * XDBL + base];
        sm[r * SROW + c] = __float2half(s);
    }
    // B tile: [128 n-rows][64 k] fp16, uint4 copies
    #pragma unroll
    for (int i = 0; i < 4; i++) {
        int e = tid + i * 256;           // 0..1023
        int r = e >> 3, c8 = (e & 7) * 8;
        *reinterpret_cast<uint4*>(sm + TA + r * SROW + c8) =
            *reinterpret_cast<const uint4*>(Bg + (size_t)(col0 + r) * 64 + c8);
    }
    __syncthreads();

    float acc[2][8][4] = {};
    uint32_t bA = smb;
    uint32_t bB = smb + (uint32_t)TA * 2u;
    const int lrow = lane & 15, lcol0 = (lane >> 4) * 8;

    #pragma unroll
    for (int kh = 0; kh < 64; kh += 32) {
        uint32_t ah[2][2][4];
        uint32_t bb[2][4][4];
        #pragma unroll
        for (int kk2 = 0; kk2 < 2; kk2++) {
            int kk = kh + kk2 * 16;
            #pragma unroll
            for (int mt = 0; mt < 2; mt++) {
                uint32_t off = (uint32_t)((wm * 32 + mt * 16 + lrow) * SROW + kk + lcol0) * 2u;
                ldm4(bA + off, ah[kk2][mt]);
            }
            #pragma unroll
            for (int g = 0; g < 4; g++) {
                uint32_t off = (uint32_t)((wn * 64 + g * 16 + lrow) * SROW + kk + lcol0) * 2u;
                ldm4(bB + off, bb[kk2][g]);
            }
        }
        #pragma unroll
        for (int kk2 = 0; kk2 < 2; kk2++) {
            #pragma unroll
            for (int g = 0; g < 4; g++) {
                #pragma unroll
                for (int mt = 0; mt < 2; mt++) {
                    mma16816(acc[mt][2 * g + 0], ah[kk2][mt], bb[kk2][g][0], bb[kk2][g][2]);
                    mma16816(acc[mt][2 * g + 1], ah[kk2][mt], bb[kk2][g][1], bb[kk2][g][3]);
                }
            }
        }
    }

    // epilogue: softplus(v + bias)
    int gq = lane >> 2, tq = lane & 3;
    #pragma unroll
    for (int mt = 0; mt < 2; mt++) {
        #pragma unroll
        for (int n8 = 0; n8 < 8; n8++) {
            int rm = row0 + wm * 32 + mt * 16 + gq;
            int cn = col0 + wn * 64 + n8 * 8 + 2 * tq;
            float v[4] = {acc[mt][n8][0], acc[mt][n8][1],
                          acc[mt][n8][2], acc[mt][n8][3]};
            float b0 = bias[cn], b1 = bias[cn + 1];
            v[0] += b0; v[1] += b1; v[2] += b0; v[3] += b1;
            #pragma unroll
            for (int q = 0; q < 4; q++)
                v[q] = (v[q] > 20.f) ? v[q] : log1pf(__expf(v[q]));
            *reinterpret_cast<float2*>(C + (size_t)rm * DI + cn) =
                make_float2(v[0], v[1]);
            *reinterpret_cast<float2*>(C + (size_t)(rm + 8) * DI + cn) =
                make_float2(v[2], v[3]);
        }
    }
}

// ---------------- fused residual-reduce + rmsnorm ----------------
__global__ void outred_rms_kernel(const float* __restrict__ norm_w,
                                  float* __restrict__ dest, int do_norm) {
    int l = blockIdx.x;
    float v[3];
    float s = 0.f;
    #pragma unroll
    for (int i = 0; i < 3; i++) {
        int d = threadIdx.x + i * 256;
        size_t idx = (size_t)l * DM + d;
        float t = g_x[idx];
        #pragma unroll
        for (int z = 0; z < 3; z++) t += g_part[(size_t)z * LSEQ * DM + idx];
        dest[idx] = t;
        v[i] = t;
        s += t * t;
    }
    if (!do_norm) return;
    __shared__ float red[8];
    #pragma unroll
    for (int o = 16; o; o >>= 1) s += __shfl_xor_sync(0xffffffffu, s, o);
    if ((threadIdx.x & 31) == 0) red[threadIdx.x >> 5] = s;
    __syncthreads();
    if (threadIdx.x < 8) {
        float t = red[threadIdx.x];
        #pragma unroll
        for (int o = 4; o; o >>= 1) t += __shfl_xor_sync(0xffu, t, o);
        if (threadIdx.x == 0) red[0] = rsqrtf(t / (float)DM + 1e-5f);
    }
    __syncthreads();
    float rinv = red[0];
    #pragma unroll
    for (int i = 0; i < 3; i++) {
        int d = threadIdx.x + i * 256;
        g_xn[(size_t)l * DM + d] = __float2half(v[i] * rinv * norm_w[d]);
    }
}

// ---------------- fused embed + rmsnorm (layer 0 entry) ----------------
__global__ void embed_rms_kernel(const int* __restrict__ ids,
                                 const float* __restrict__ emb,
                                 const float* __restrict__ norm_w) {
    int l = blockIdx.x;
    const float* erow = emb + (size_t)ids[l] * DM;
    float v[3];
    float s = 0.f;
    #pragma unroll
    for (int i = 0; i < 3; i++) {
        int d = threadIdx.x + i * 256;
        float t = erow[d];
        g_x[(size_t)l * DM + d] = t;
        v[i] = t;
        s += t * t;
    }
    __shared__ float red[8];
    #pragma unroll
    for (int o = 16; o; o >>= 1) s += __shfl_xor_sync(0xffffffffu, s, o);
    if ((threadIdx.x & 31) == 0) red[threadIdx.x >> 5] = s;
    __syncthreads();
    if (threadIdx.x < 8) {
        float t = red[threadIdx.x];
        #pragma unroll
        for (int o = 4; o; o >>= 1) t += __shfl_xor_sync(0xffu, t, o);
        if (threadIdx.x == 0) red[0] = rsqrtf(t / (float)DM + 1e-5f);
    }
    __syncthreads();
    float rinv = red[0];
    #pragma unroll
    for (int i = 0; i < 3; i++) {
        int d = threadIdx.x + i * 256;
        g_xn[(size_t)l * DM + d] = __float2half(v[i] * rinv * norm_w[d]);
    }
}

// ---------------- fused weight prep (all transposes, both layers) ----------------
#define WP_TIN  2304
#define WP_TOUT 1152
#define WP_TXP  192
#define WP_TDT  96
#define WP_PER_LAYER (WP_TIN + WP_TOUT + WP_TXP + WP_TDT)

__device__ __forceinline__ void wp_tile(const float* __restrict__ W,
                                        __half* __restrict__ out,
                                        int Kin, int Kpad, int N, int Npad,
                                        int k0, int n0) {
    __shared__ float t[32][33];
    #pragma unroll
    for (int i = 0; i < 4; i++) {
        int k = k0 + threadIdx.y + i * 8;
        int n = n0 + threadIdx.x;
        t[threadIdx.y + i * 8][threadIdx.x] =
            (k < Kin && n < N) ? W[(size_t)k * N + n] : 0.f;
    }
    __syncthreads();
    #pragma unroll
    for (int i = 0; i < 4; i++) {
        int n = n0 + threadIdx.y + i * 8;
        int k = k0 + threadIdx.x;
        if (n < Npad && k < Kpad)
            out[(size_t)n * Kpad + k] = __float2half(t[threadIdx.x][threadIdx.y + i * 8]);
    }
}

__global__ void wprep_kernel(const float* __restrict__ in_proj_w,
                             const float* __restrict__ out_proj_w,
                             const float* __restrict__ x_proj_w,
                             const float* __restrict__ dt_proj_w) {
    int layer = blockIdx.y;
    int b = blockIdx.x;
    if (b < WP_TIN) {
        int kt = b % 24, nt = b / 24;
        wp_tile(in_proj_w + (size_t)layer * DM * DXZ,
                g_win + (size_t)layer * DM * DXZ,
                DM, DM, DXZ, DXZ, kt * 32, nt * 32);
        return;
    }
    b -= WP_TIN;
    if (b < WP_TOUT) {
        int kt = b % 48, nt = b / 48;
        wp_tile(out_proj_w + (size_t)layer * DI * DM,
                g_wout + (size_t)layer * DI * DM,
                DI, DI, DM, DM, kt * 32, nt * 32);
        return;
    }
    b -= WP_TOUT;
    if (b < WP_TXP) {
        int kt = b % 48, nt = b / 48;
        wp_tile(x_proj_w + (size_t)layer * DI * XDBL,
                g_wxp + (size_t)layer * 128 * DI,
                DI, DI, XDBL, 128, kt * 32, nt * 32);
        return;
    }
    b -= WP_TXP;
    {
        int kt = b % 2, nt = b / 2;
        wp_tile(dt_proj_w + (size_t)layer * DTR * DI,
                g_wdt + (size_t)layer * DI * 64,
                DTR, 64, DI, DI, kt * 32, nt * 32);
    }
}

// conv + silu: 8 outputs along l per thread, taps reused in registers
__global__ void conv_silu_kernel(const float* __restrict__ w,
                                 const float* __restrict__ b) {
    int d = blockIdx.x * 256 + threadIdx.x;
    int l0 = blockIdx.y * 8;
    float w0 = w[d * DCONV + 0], w1 = w[d * DCONV + 1];
    float w2 = w[d * DCONV + 2], w3 = w[d * DCONV + 3];
    float bb = b[d];
    float x[11];
    #pragma unroll
    for (int t = 0; t < 11; t++) {
        int ll = l0 - 3 + t;
        x[t] = (ll >= 0 && ll < LSEQ) ? g_xz[(size_t)ll * DXZ + d] : 0.f;
    }
    #pragma unroll
    for (int j = 0; j < 8; j++) {
        float s = bb;
        s = fmaf(w0, x[j + 0], s);
        s = fmaf(w1, x[j + 1], s);
        s = fmaf(w2, x[j + 2], s);
        s = fmaf(w3, x[j + 3], s);
        float sig = 1.f / (1.f + __expf(-s));
        float v = s * sig;
        size_t idx = (size_t)(l0 + j) * DI + d;
        g_xr[idx] = v;
        g_xrh[idx] = __float2half(v);
    }
}

// ---------------- chunked selective scan (power-chain exp) ----------------
// sB/sC prologues sum the 8 x_proj split-K partials directly (z order 0..7,
// identical to the old reduce kernel -> bit-identical results).
__global__ void scan_phaseA_kernel(const float* __restrict__ A_log) {
    int d = blockIdx.x * blockDim.x + threadIdx.x;
    int chunk = blockIdx.y;
    __shared__ float sB[CLEN][DS];
    int l0 = chunk * CLEN;
    for (int idx = threadIdx.x; idx < CLEN * DS; idx += blockDim.x) {
        int l = idx >> 4, n = idx & 15;
        size_t base = (size_t)(l0 + l) * XDBL + DTR + n;
        float s = 0.f;
        #pragma unroll
        for (int z = 0; z < 8; z++) s += g_part[(size_t)z * LSEQ * XDBL + base];
        sB[l][n] = s;
    }
    __syncthreads();

    float Arow[DS], h[DS], P[DS];
    bool chain = true;
    #pragma unroll
    for (int n = 0; n < DS; n++) {
        Arow[n] = -__expf(A_log[(size_t)d * DS + n]);
        h[n] = 0.f; P[n] = 1.f;
    }
    float r0 = Arow[0];
    #pragma unroll
    for (int n = 1; n < DS; n++)
        chain = chain && (fabsf(Arow[n] - (float)(n + 1) * r0)
                          <= 1e-5f * fabsf(Arow[n]) + 1e-7f);

    if (chain) {
        for (int l = 0; l < CLEN; l++) {
            float dl = g_delta[(size_t)(l0 + l) * DI + d];
            float du = dl * g_xr[(size_t)(l0 + l) * DI + d];
            float q = __expf(dl * r0);
            float a = 1.f;
            #pragma unroll
            for (int n = 0; n < DS; n++) {
                a *= q;
                h[n] = fmaf(a, h[n], du * sB[l][n]);
                P[n] *= a;
            }
        }
    } else {
        for (int l = 0; l < CLEN; l++) {
            float dl = g_delta[(size_t)(l0 + l) * DI + d];
            float du = dl * g_xr[(size_t)(l0 + l) * DI + d];
            #pragma unroll
            for (int n = 0; n < DS; n++) {
                float a = __expf(dl * Arow[n]);
                h[n] = fmaf(a, h[n], du * sB[l][n]);
                P[n] *= a;
            }
        }
    }
    size_t base = ((size_t)chunk * DI + d) * DS;
    #pragma unroll
    for (int n = 0; n < DS; n++) {
        g_Aprod[base + n] = P[n];
        g_Hend [base + n] = h[n];
    }
}

__global__ void scan_phaseB_kernel() {
    int i = blockIdx.x * blockDim.x + threadIdx.x;
    if (i >= DI * DS) return;
    float run = 0.f;
    #pragma unroll 8
    for (int c = 0; c < NCH; c++) {
        size_t idx = (size_t)c * DI * DS + i;
        g_Hinit[idx] = run;
        run = fmaf(g_Aprod[idx], run, g_Hend[idx]);
    }
}

__global__ void scan_phaseC_kernel(const float* __restrict__ A_log,
                                   const float* __restrict__ Dp) {
    int d = blockIdx.x * blockDim.x + threadIdx.x;
    int chunk = blockIdx.y;
    __shared__ float sB[CLEN][DS];
    __shared__ float sC[CLEN][DS];
    int l0 = chunk * CLEN;
    for (int idx = threadIdx.x; idx < CLEN * DS; idx += blockDim.x) {
        int l = idx >> 4, n = idx & 15;
        size_t baseB = (size_t)(l0 + l) * XDBL + DTR + n;
        float sb = 0.f, sc = 0.f;
        #pragma unroll
        for (int z = 0; z < 8; z++) {
            sb += g_part[(size_t)z * LSEQ * XDBL + baseB];
            sc += g_part[(size_t)z * LSEQ * XDBL + baseB + DS];
        }
        sB[l][n] = sb;
        sC[l][n] = sc;
    }
    __syncthreads();

    float Arow[DS], h[DS];
    bool chain = true;
    size_t base = ((size_t)chunk * DI + d) * DS;
    #pragma unroll
    for (int n = 0; n < DS; n++) {
        Arow[n] = -__expf(A_log[(size_t)d * DS + n]);
        h[n] = g_Hinit[base + n];
    }
    float r0 = Arow[0];
    #pragma unroll
    for (int n = 1; n < DS; n++)
        chain = chain && (fabsf(Arow[n] - (float)(n + 1) * r0)
                          <= 1e-5f * fabsf(Arow[n]) + 1e-7f);
    float Dd = Dp[d];

    for (int l = 0; l < CLEN; l++) {
        float dl = g_delta[(size_t)(l0 + l) * DI + d];
        float u  = g_xr[(size_t)(l0 + l) * DI + d];
        float du = dl * u;
        float y = 0.f;
        if (chain) {
            float q = __expf(dl * r0);
            float a = 1.f;
            #pragma unroll
            for (int n = 0; n < DS; n++) {
                a *= q;
                h[n] = fmaf(a, h[n], du * sB[l][n]);
                y = fmaf(h[n], sC[l][n], y);
            }
        } else {
            #pragma unroll
            for (int n = 0; n < DS; n++) {
                float a = __expf(dl * Arow[n]);
                h[n] = fmaf(a, h[n], du * sB[l][n]);
                y = fmaf(h[n], sC[l][n], y);
            }
        }
        y = fmaf(u, Dd, y);
        float res = g_xz[(size_t)(l0 + l) * DXZ + DI + d];
        float sig = 1.f / (1.f + __expf(-res));
        g_ya[(size_t)(l0 + l) * DI + d] = __float2half(y * (res * sig));
    }
}

// ---------------- launcher ----------------
extern "C" void kernel_launch(void* const* d_in, const int* in_sizes, int n_in,
                              void* d_out, int out_size) {
    const int*   ids        = (const int*)  d_in[0];
    const float* emb        = (const float*)d_in[1];
    const float* norm_w     = (const float*)d_in[2];
    const float* in_proj_w  = (const float*)d_in[3];
    const float* conv_w     = (const float*)d_in[4];
    const float* conv_b     = (const float*)d_in[5];
    const float* x_proj_w   = (const float*)d_in[6];
    const float* dt_proj_w  = (const float*)d_in[7];
    const float* dt_proj_b  = (const float*)d_in[8];
    const float* A_log      = (const float*)d_in[9];
    const float* Dp         = (const float*)d_in[10];
    const float* out_proj_w = (const float*)d_in[11];
    float* out = (float*)d_out;

    cudaFuncSetAttribute(gemm_fp16_kernel,
                         cudaFuncAttributeMaxDynamicSharedMemorySize, SMEM_MMA);
    cudaFuncSetAttribute(dtproj_kernel,
                         cudaFuncAttributeMaxDynamicSharedMemorySize, SMEM_DT);

    __half *xn, *xrh, *ya, *win, *wout, *wxp, *wdt;
    float *xz, *x_res, *part, *delta;
    cudaGetSymbolAddress((void**)&xn,    g_xn);
    cudaGetSymbolAddress((void**)&xrh,   g_xrh);
    cudaGetSymbolAddress((void**)&ya,    g_ya);
    cudaGetSymbolAddress((void**)&win,   g_win);
    cudaGetSymbolAddress((void**)&wout,  g_wout);
    cudaGetSymbolAddress((void**)&wxp,   g_wxp);
    cudaGetSymbolAddress((void**)&wdt,   g_wdt);
    cudaGetSymbolAddress((void**)&xz,    g_xz);
    cudaGetSymbolAddress((void**)&x_res, g_x);
    cudaGetSymbolAddress((void**)&part,  g_part);
    cudaGetSymbolAddress((void**)&delta, g_delta);

    wprep_kernel<<<dim3(WP_PER_LAYER, NLAYER), dim3(32, 8)>>>(
        in_proj_w, out_proj_w, x_proj_w, dt_proj_w);

    embed_rms_kernel<<<LSEQ, 256>>>(ids, emb, norm_w);

    for (int layer = 0; layer < NLAYER; layer++) {
        const __half* wt_in  = win  + (size_t)layer * DM * DXZ;
        const __half* wt_out = wout + (size_t)layer * DI * DM;
        const __half* wt_xp  = wxp  + (size_t)layer * 128 * DI;
        const __half* wt_dt  = wdt  + (size_t)layer * DI * 64;

        // in_proj: M128 tile (round-8 optimum)
        gemm_fp16_kernel<<<dim3(DXZ / 128, LSEQ / 128, 1), 256, SMEM_MMA>>>(
            xn, wt_in, xz, DM, DM, DXZ, DXZ);

        conv_silu_kernel<<<dim3(DI / 256, LSEQ / 8), 256>>>(
            conv_w + (size_t)layer * DI * DCONV,
            conv_b + (size_t)layer * DI);

        // x_proj: split-K 8 (ksize 192), partials consumed by dtproj + scans
        gemm_fp16_kernel<<<dim3(1, LSEQ / 128, 8), 256, SMEM_MMA>>>(
            xrh, wt_xp, part, DI, DI / 8, XDBL, XDBL);

        // dt_proj: fused partial-reduce A-tile, softplus+bias epilogue
        dtproj_kernel<<<dim3(DI / 128, LSEQ / 128), 256, SMEM_DT>>>(
            wt_dt, delta, dt_proj_b + (size_t)layer * DI);

        scan_phaseA_kernel<<<dim3(DI / 128, NCH), 128>>>(
            A_log + (size_t)layer * DI * DS);
        scan_phaseB_kernel<<<(DI * DS + 255) / 256, 256>>>();
        scan_phaseC_kernel<<<dim3(DI / 128, NCH), 128>>>(
            A_log + (size_t)layer * DI * DS,
            Dp + (size_t)layer * DI);

        // out_proj: split-K 3 + fused reduce/rms
        gemm_fp16_kernel<<<dim3(DM / 128, LSEQ / 128, 3), 256, SMEM_MMA>>>(
            ya, wt_out, part, DI, DI / 3, DM, DM);

        if (layer == NLAYER - 1) {
            outred_rms_kernel<<<LSEQ, 256>>>(nullptr, out, 0);
        } else {
            outred_rms_kernel<<<LSEQ, 256>>>(norm_w + (size_t)(layer + 1) * DM,
                                             x_res, 1);
        }
    }
}